// round 2
// baseline (speedup 1.0000x reference)
#include <cuda_runtime.h>
#include <cuda_bf16.h>
#include <float.h>

#define BB     64
#define SS     2048
#define HH     2048
#define HQ     16
#define HKV    4
#define DD     128
#define RDIM   64
#define GG     4
#define CQKV   3072          // HQ*D + 2*HKV*D
#define SKN    4             // split-K factor
#define KCH    (HH / SKN)    // 512
#define CHUNK  256
#define NSPLIT (SS / CHUNK)  // 8
#define EPSV   1e-6f
#define SCALEV 0.08838834764831843f  // 128^-0.5

// ---------------- scratch (device globals; no allocs allowed) ---------------
__device__ float g_qkv_part[SKN * BB * CQKV];          // 3 MB
__device__ float g_qbuf[BB * HQ * DD];                 // q, pre-scaled
__device__ float g_knew[BB * HKV * DD];
__device__ float g_vnew[BB * HKV * DD];
__device__ float g_po[BB * HKV * NSPLIT * GG * DD];    // 4 MB partial O
__device__ float g_pm[BB * HKV * NSPLIT * GG];
__device__ float g_pl[BB * HKV * NSPLIT * GG];
__device__ float g_attn[BB * HQ * DD];
__device__ float g_wo_part[SKN * BB * HH];             // 2 MB

// ---------------- skinny split-K SGEMM: out[b][c] = sum_k X[b][k]*W[c][k] ---
// SEL==0: X = Xin (hidden), out = g_qkv_part; SEL==1: X = g_attn, out = g_wo_part
template <int SEL>
__global__ void __launch_bounds__(256)
sgemm_part(const float* __restrict__ Xin,
           const float* __restrict__ W1,
           const float* __restrict__ W2,
           const float* __restrict__ W3,
           int c1, int c2, int C)
{
    const float* X    = (SEL == 0) ? Xin : g_attn;
    float*       outp = (SEL == 0) ? g_qkv_part : g_wo_part;

    int n0 = blockIdx.x * 64;
    int sk = blockIdx.y;
    const float* W; int woff;
    if (n0 < c1)      { W = W1; woff = 0;  }
    else if (n0 < c2) { W = W2; woff = c1; }
    else              { W = W3; woff = c2; }
    const float* Wb = W + (size_t)(n0 - woff) * HH;

    __shared__ __align__(16) float As[16][64];
    __shared__ __align__(16) float Bs[16][64];

    int tid = threadIdx.x;
    int lr  = tid >> 2;          // 0..63 (row within tile for loading)
    int lc  = (tid & 3) << 2;    // 0,4,8,12 (k offset, float4)
    int ty  = tid >> 4;          // 0..15
    int tx  = tid & 15;          // 0..15

    float acc[4][4] = {};
    int kbase = sk * KCH;

    for (int kt = 0; kt < KCH; kt += 16) {
        int k0 = kbase + kt;
        float4 av = *(const float4*)(X  + (size_t)lr * HH + k0 + lc);
        float4 bv = *(const float4*)(Wb + (size_t)lr * HH + k0 + lc);
        __syncthreads();
        As[lc + 0][lr] = av.x; As[lc + 1][lr] = av.y;
        As[lc + 2][lr] = av.z; As[lc + 3][lr] = av.w;
        Bs[lc + 0][lr] = bv.x; Bs[lc + 1][lr] = bv.y;
        Bs[lc + 2][lr] = bv.z; Bs[lc + 3][lr] = bv.w;
        __syncthreads();
#pragma unroll
        for (int k = 0; k < 16; k++) {
            float4 a  = *(const float4*)&As[k][ty * 4];
            float4 b4 = *(const float4*)&Bs[k][tx * 4];
            acc[0][0] += a.x * b4.x; acc[0][1] += a.x * b4.y;
            acc[0][2] += a.x * b4.z; acc[0][3] += a.x * b4.w;
            acc[1][0] += a.y * b4.x; acc[1][1] += a.y * b4.y;
            acc[1][2] += a.y * b4.z; acc[1][3] += a.y * b4.w;
            acc[2][0] += a.z * b4.x; acc[2][1] += a.z * b4.y;
            acc[2][2] += a.z * b4.z; acc[2][3] += a.z * b4.w;
            acc[3][0] += a.w * b4.x; acc[3][1] += a.w * b4.y;
            acc[3][2] += a.w * b4.z; acc[3][3] += a.w * b4.w;
        }
    }

    float* op = outp + (size_t)sk * BB * C;
#pragma unroll
    for (int i = 0; i < 4; i++) {
        *(float4*)&op[(size_t)(ty * 4 + i) * C + n0 + tx * 4] =
            make_float4(acc[i][0], acc[i][1], acc[i][2], acc[i][3]);
    }
}

// ---------------- split-K reduce + RMSNorm + RoPE + staging ------------------
__global__ void __launch_bounds__(128)
rms_rope_kernel(const float* __restrict__ qw, const float* __restrict__ kw,
                const float* __restrict__ cosp, const float* __restrict__ sinp)
{
    int b  = blockIdx.x;
    int hh = blockIdx.y;   // 0..23: [0,16) q, [16,20) k, [20,24) v
    int d  = threadIdx.x;  // 0..127

    int col, kind;
    if (hh < HQ)            { kind = 0; col = hh * DD + d; }
    else if (hh < HQ + HKV) { kind = 1; col = HH + (hh - HQ) * DD + d; }
    else                    { kind = 2; col = HH + HKV * DD + (hh - HQ - HKV) * DD + d; }

    float val = 0.f;
#pragma unroll
    for (int s = 0; s < SKN; s++)
        val += g_qkv_part[(size_t)s * BB * CQKV + (size_t)b * CQKV + col];

    if (kind == 2) {  // v: no norm, no rope
        g_vnew[(b * HKV + (hh - HQ - HKV)) * DD + d] = val;
        return;
    }

    __shared__ float red[4];
    __shared__ float xs[DD];

    float sq = val * val;
#pragma unroll
    for (int o = 16; o > 0; o >>= 1) sq += __shfl_xor_sync(0xffffffffu, sq, o);
    if ((d & 31) == 0) red[d >> 5] = sq;
    __syncthreads();
    float var = (red[0] + red[1] + red[2] + red[3]) * (1.f / DD);
    float r   = rsqrtf(var + EPSV);

    const float* w = (kind == 0) ? qw : kw;
    val = w[d] * val * r;
    xs[d] = val;
    __syncthreads();

    float outv = val;
    if (d < RDIM) {
        float c  = cosp[b * RDIM + d];
        float s2 = sinp[b * RDIM + d];
        float other = (d < RDIM / 2) ? -xs[d + RDIM / 2] : xs[d - RDIM / 2];
        outv = val * c + other * s2;
    }
    if (kind == 0) g_qbuf[(b * HQ + hh) * DD + d] = outv * SCALEV;  // fold score scale
    else           g_knew[(b * HKV + (hh - HQ)) * DD + d] = outv;
}

// ---------------- flash-decode partial attention ----------------------------
__global__ void __launch_bounds__(256)
attn_partial(const float* __restrict__ kc, const float* __restrict__ vc,
             const int* __restrict__ r2t, const int* __restrict__ rpi,
             const int* __restrict__ slen, const int* __restrict__ loc)
{
    int b  = blockIdx.x;
    int kv = blockIdx.y;
    int sp = blockIdx.z;
    int L  = slen[b];
    int start = sp * CHUNK;
    if (start >= L) return;
    int end = min(start + CHUNK, L);
    int n   = end - start;

    int tid  = threadIdx.x;
    int w    = tid >> 5;
    int lane = tid & 31;
    int myloc = loc[b];
    int rbase = rpi[b] * SS;

    __shared__ __align__(16) float qs[GG][DD];   // 2 KB
    __shared__ float sc[GG][CHUNK];              // 4 KB (scores -> probs)
    __shared__ int   tok_s[CHUNK];               // 1 KB
    __shared__ float red[8];

    for (int i = tid; i < GG * DD; i += 256)
        qs[i >> 7][i & 127] = g_qbuf[(b * HQ + kv * GG + (i >> 7)) * DD + (i & 127)];
    for (int t = tid; t < n; t += 256)
        tok_s[t] = r2t[rbase + start + t];
    __syncthreads();

    // Phase 1: scores (q pre-scaled). One warp per token; coalesced 512B K-row.
    const float* knewp = g_knew + (b * HKV + kv) * DD;
    for (int t0 = w; t0 < n; t0 += 8) {
        int tk = tok_s[t0];
        const float* kp = (tk == myloc) ? knewp
                                        : (kc + ((size_t)tk * HKV + kv) * DD);
        float4 k4 = *((const float4*)kp + lane);
        float4 q0 = *((const float4*)&qs[0][0] + lane);
        float4 q1 = *((const float4*)&qs[1][0] + lane);
        float4 q2 = *((const float4*)&qs[2][0] + lane);
        float4 q3 = *((const float4*)&qs[3][0] + lane);
        float s0 = k4.x * q0.x + k4.y * q0.y + k4.z * q0.z + k4.w * q0.w;
        float s1 = k4.x * q1.x + k4.y * q1.y + k4.z * q1.z + k4.w * q1.w;
        float s2 = k4.x * q2.x + k4.y * q2.y + k4.z * q2.z + k4.w * q2.w;
        float s3 = k4.x * q3.x + k4.y * q3.y + k4.z * q3.z + k4.w * q3.w;
#pragma unroll
        for (int o = 16; o > 0; o >>= 1) {
            s0 += __shfl_xor_sync(0xffffffffu, s0, o);
            s1 += __shfl_xor_sync(0xffffffffu, s1, o);
            s2 += __shfl_xor_sync(0xffffffffu, s2, o);
            s3 += __shfl_xor_sync(0xffffffffu, s3, o);
        }
        if (lane == 0) {
            sc[0][t0] = s0; sc[1][t0] = s1; sc[2][t0] = s2; sc[3][t0] = s3;
        }
    }
    __syncthreads();

    // Phase 2: per-g chunk max, exp, sum; store (m, l).
    int mlbase = ((b * HKV + kv) * NSPLIT + sp) * GG;
#pragma unroll
    for (int g = 0; g < GG; g++) {
        float v  = (tid < n) ? sc[g][tid] : -FLT_MAX;
        float mv = v;
#pragma unroll
        for (int o = 16; o > 0; o >>= 1)
            mv = fmaxf(mv, __shfl_xor_sync(0xffffffffu, mv, o));
        if (lane == 0) red[w] = mv;
        __syncthreads();
        float mg = red[0];
#pragma unroll
        for (int i = 1; i < 8; i++) mg = fmaxf(mg, red[i]);
        float e = (tid < n) ? __expf(v - mg) : 0.f;
        if (tid < n) sc[g][tid] = e;
        float sv = e;
#pragma unroll
        for (int o = 16; o > 0; o >>= 1)
            sv += __shfl_xor_sync(0xffffffffu, sv, o);
        __syncthreads();                 // all mg reads done before overwrite
        if (lane == 0) red[w] = sv;
        __syncthreads();
        if (tid == 0) {
            float lg = 0.f;
#pragma unroll
            for (int i = 0; i < 8; i++) lg += red[i];
            g_pm[mlbase + g] = mg;
            g_pl[mlbase + g] = lg;
        }
        __syncthreads();                 // protect red for next g
    }

    // Phase 3: PV. 128 d-threads x 2 head-groups; coalesced 512B V-rows.
    int grp = tid >> 7;
    int d   = tid & 127;
    int g0  = grp * 2, g1 = g0 + 1;
    float a0 = 0.f, a1 = 0.f;
    const float* vnewp = g_vnew + (b * HKV + kv) * DD;
#pragma unroll 4
    for (int t = 0; t < n; t++) {
        int tk = tok_s[t];
        const float* vp = (tk == myloc) ? vnewp
                                        : (vc + ((size_t)tk * HKV + kv) * DD);
        float vv = vp[d];
        a0 = fmaf(sc[g0][t], vv, a0);
        a1 = fmaf(sc[g1][t], vv, a1);
    }
    int ob = ((b * HKV + kv) * NSPLIT + sp) * GG * DD;
    g_po[ob + g0 * DD + d] = a0;
    g_po[ob + g1 * DD + d] = a1;
}

// ---------------- combine splits (logsumexp) --------------------------------
__global__ void __launch_bounds__(128)
combine_kernel(const int* __restrict__ slen)
{
    int b = blockIdx.x;
    int h = blockIdx.y;            // 0..15 global q head
    int kv = h >> 2, g = h & 3;
    int d  = threadIdx.x;
    int L  = slen[b];
    int ns = (L + CHUNK - 1) / CHUNK;

    int mlbase = ((b * HKV + kv) * NSPLIT) * GG + g;
    float M = -FLT_MAX;
    for (int i = 0; i < ns; i++) M = fmaxf(M, g_pm[mlbase + i * GG]);

    float denom = 0.f, acc = 0.f;
    int obase = ((b * HKV + kv) * NSPLIT) * GG * DD + g * DD + d;
    for (int i = 0; i < ns; i++) {
        float wgt = __expf(g_pm[mlbase + i * GG] - M);
        denom += wgt * g_pl[mlbase + i * GG];
        acc   += wgt * g_po[obase + i * GG * DD];
    }
    g_attn[(b * HQ + h) * DD + d] = acc / denom;
}

// ---------------- Wo split-K reduce -> final output -------------------------
__global__ void __launch_bounds__(256)
wo_reduce(float* __restrict__ out)
{
    int i = blockIdx.x * 256 + threadIdx.x;   // 0..131071
    out[i] = g_wo_part[i]
           + g_wo_part[1 * BB * HH + i]
           + g_wo_part[2 * BB * HH + i]
           + g_wo_part[3 * BB * HH + i];
}

// ---------------- launch -----------------------------------------------------
extern "C" void kernel_launch(void* const* d_in, const int* in_sizes, int n_in,
                              void* d_out, int out_size)
{
    const float* hid  = (const float*)d_in[0];
    const float* Wq   = (const float*)d_in[1];
    const float* Wk   = (const float*)d_in[2];
    const float* Wv   = (const float*)d_in[3];
    const float* qw   = (const float*)d_in[4];
    const float* kw   = (const float*)d_in[5];
    const float* Wo   = (const float*)d_in[6];
    const float* kc   = (const float*)d_in[7];
    const float* vc   = (const float*)d_in[8];
    const float* cosp = (const float*)d_in[9];
    const float* sinp = (const float*)d_in[10];
    const int*   r2t  = (const int*)d_in[11];
    const int*   rpi  = (const int*)d_in[12];
    const int*   slen = (const int*)d_in[13];
    const int*   loc  = (const int*)d_in[14];
    float* out = (float*)d_out;

    sgemm_part<0><<<dim3(CQKV / 64, SKN), 256>>>(hid, Wq, Wk, Wv, HH, HH + HKV * DD, CQKV);
    rms_rope_kernel<<<dim3(BB, HQ + 2 * HKV), 128>>>(qw, kw, cosp, sinp);
    attn_partial<<<dim3(BB, HKV, NSPLIT), 256>>>(kc, vc, r2t, rpi, slen, loc);
    combine_kernel<<<dim3(BB, HQ), 128>>>(slen);
    sgemm_part<1><<<dim3(HH / 64, SKN), 256>>>(nullptr, Wo, Wo, Wo, 2 * HH, 2 * HH, HH);
    wo_reduce<<<BB * HH / 256, 256>>>(out);
}

// round 3
// speedup vs baseline: 1.2035x; 1.2035x over previous
#include <cuda_runtime.h>
#include <cuda_bf16.h>
#include <float.h>

#define BB     64
#define SS     2048
#define HH     2048
#define HQ     16
#define HKV    4
#define DD     128
#define RDIM   64
#define GG     4
#define CQKV   3072          // HQ*D + 2*HKV*D
#define SKN    8             // split-K factor
#define KCH    (HH / SKN)    // 256
#define CHUNK  256
#define NSPLIT (SS / CHUNK)  // 8
#define EPSV   1e-6f
#define SCALEV 0.08838834764831843f  // 128^-0.5

// ---------------- scratch (device globals; no allocs allowed) ---------------
__device__ float g_qkv_part[SKN * BB * CQKV];          // 6.3 MB
__device__ float g_qbuf[BB * HQ * DD];                 // q, pre-scaled
__device__ float g_knew[BB * HKV * DD];
__device__ float g_vnew[BB * HKV * DD];
__device__ float g_po[BB * HKV * NSPLIT * GG * DD];    // 4 MB partial O
__device__ float g_pm[BB * HKV * NSPLIT * GG];
__device__ float g_pl[BB * HKV * NSPLIT * GG];
__device__ float g_attn[BB * HQ * DD];
__device__ float g_wo_part[SKN * BB * HH];             // 4.2 MB

// ---------------- skinny split-K SGEMM: out[b][c] = sum_k X[b][k]*W[c][k] ---
// Tile: 64 rows (all of B) x 128 cols, Kc=16 per stage, 256 threads,
// 4x8 microtile, register-staged global prefetch.
// SEL==0: X = Xin (hidden), out = g_qkv_part; SEL==1: X = g_attn, out = g_wo_part
template <int SEL>
__global__ void __launch_bounds__(256)
sgemm_part(const float* __restrict__ Xin,
           const float* __restrict__ W1,
           const float* __restrict__ W2,
           const float* __restrict__ W3,
           int c1, int c2, int C)
{
    const float* X    = (SEL == 0) ? Xin : g_attn;
    float*       outp = (SEL == 0) ? g_qkv_part : g_wo_part;

    int n0 = blockIdx.x * 128;
    int sk = blockIdx.y;
    const float* W; int woff;
    if (n0 < c1)      { W = W1; woff = 0;  }
    else if (n0 < c2) { W = W2; woff = c1; }
    else              { W = W3; woff = c2; }
    const float* Wb = W + (size_t)(n0 - woff) * HH;

    __shared__ __align__(16) float As[16][64];    // 4 KB
    __shared__ __align__(16) float Bs[16][128];   // 8 KB

    int tid = threadIdx.x;
    int r   = tid >> 2;          // 0..63
    int kc  = (tid & 3) << 2;    // 0,4,8,12
    int ty  = tid >> 4;          // 0..15 -> rows ty*4..ty*4+3
    int tx  = tid & 15;          // 0..15 -> cols tx*8..tx*8+7

    int kbase = sk * KCH;
    const float* xp = X  + (size_t)r * HH + kbase + kc;
    const float* w0 = Wb + (size_t)r * HH + kbase + kc;
    const float* w1 = Wb + (size_t)(r + 64) * HH + kbase + kc;

    float4 ax = *(const float4*)xp;
    float4 b0 = *(const float4*)w0;
    float4 b1 = *(const float4*)w1;

    float acc[4][8] = {};

    for (int kt = 0; kt < KCH; kt += 16) {
        As[kc + 0][r] = ax.x; As[kc + 1][r] = ax.y;
        As[kc + 2][r] = ax.z; As[kc + 3][r] = ax.w;
        Bs[kc + 0][r] = b0.x; Bs[kc + 1][r] = b0.y;
        Bs[kc + 2][r] = b0.z; Bs[kc + 3][r] = b0.w;
        Bs[kc + 0][r + 64] = b1.x; Bs[kc + 1][r + 64] = b1.y;
        Bs[kc + 2][r + 64] = b1.z; Bs[kc + 3][r + 64] = b1.w;
        __syncthreads();

        if (kt + 16 < KCH) {                 // prefetch next stage during compute
            ax = *(const float4*)(xp + kt + 16);
            b0 = *(const float4*)(w0 + kt + 16);
            b1 = *(const float4*)(w1 + kt + 16);
        }

#pragma unroll
        for (int k = 0; k < 16; k++) {
            float4 a  = *(const float4*)&As[k][ty * 4];
            float4 bA = *(const float4*)&Bs[k][tx * 8];
            float4 bB = *(const float4*)&Bs[k][tx * 8 + 4];
            float av[4] = {a.x, a.y, a.z, a.w};
#pragma unroll
            for (int i = 0; i < 4; i++) {
                acc[i][0] = fmaf(av[i], bA.x, acc[i][0]);
                acc[i][1] = fmaf(av[i], bA.y, acc[i][1]);
                acc[i][2] = fmaf(av[i], bA.z, acc[i][2]);
                acc[i][3] = fmaf(av[i], bA.w, acc[i][3]);
                acc[i][4] = fmaf(av[i], bB.x, acc[i][4]);
                acc[i][5] = fmaf(av[i], bB.y, acc[i][5]);
                acc[i][6] = fmaf(av[i], bB.z, acc[i][6]);
                acc[i][7] = fmaf(av[i], bB.w, acc[i][7]);
            }
        }
        __syncthreads();
    }

    float* op = outp + (size_t)sk * BB * C;
#pragma unroll
    for (int i = 0; i < 4; i++) {
        *(float4*)&op[(size_t)(ty * 4 + i) * C + n0 + tx * 8] =
            make_float4(acc[i][0], acc[i][1], acc[i][2], acc[i][3]);
        *(float4*)&op[(size_t)(ty * 4 + i) * C + n0 + tx * 8 + 4] =
            make_float4(acc[i][4], acc[i][5], acc[i][6], acc[i][7]);
    }
}

// ---------------- split-K reduce + RMSNorm + RoPE + staging ------------------
__global__ void __launch_bounds__(128)
rms_rope_kernel(const float* __restrict__ qw, const float* __restrict__ kw,
                const float* __restrict__ cosp, const float* __restrict__ sinp)
{
    int b  = blockIdx.x;
    int hh = blockIdx.y;   // 0..23: [0,16) q, [16,20) k, [20,24) v
    int d  = threadIdx.x;  // 0..127

    int col, kind;
    if (hh < HQ)            { kind = 0; col = hh * DD + d; }
    else if (hh < HQ + HKV) { kind = 1; col = HH + (hh - HQ) * DD + d; }
    else                    { kind = 2; col = HH + HKV * DD + (hh - HQ - HKV) * DD + d; }

    float val = 0.f;
#pragma unroll
    for (int s = 0; s < SKN; s++)
        val += g_qkv_part[(size_t)s * BB * CQKV + (size_t)b * CQKV + col];

    if (kind == 2) {  // v: no norm, no rope
        g_vnew[(b * HKV + (hh - HQ - HKV)) * DD + d] = val;
        return;
    }

    __shared__ float red[4];
    __shared__ float xs[DD];

    float sq = val * val;
#pragma unroll
    for (int o = 16; o > 0; o >>= 1) sq += __shfl_xor_sync(0xffffffffu, sq, o);
    if ((d & 31) == 0) red[d >> 5] = sq;
    __syncthreads();
    float var = (red[0] + red[1] + red[2] + red[3]) * (1.f / DD);
    float r   = rsqrtf(var + EPSV);

    const float* w = (kind == 0) ? qw : kw;
    val = w[d] * val * r;
    xs[d] = val;
    __syncthreads();

    float outv = val;
    if (d < RDIM) {
        float c  = cosp[b * RDIM + d];
        float s2 = sinp[b * RDIM + d];
        float other = (d < RDIM / 2) ? -xs[d + RDIM / 2] : xs[d - RDIM / 2];
        outv = val * c + other * s2;
    }
    if (kind == 0) g_qbuf[(b * HQ + hh) * DD + d] = outv * SCALEV;  // fold score scale
    else           g_knew[(b * HKV + (hh - HQ)) * DD + d] = outv;
}

// ---------------- flash-decode partial attention ----------------------------
__global__ void __launch_bounds__(256)
attn_partial(const float* __restrict__ kc, const float* __restrict__ vc,
             const int* __restrict__ r2t, const int* __restrict__ rpi,
             const int* __restrict__ slen, const int* __restrict__ loc)
{
    int b  = blockIdx.x;
    int kv = blockIdx.y;
    int sp = blockIdx.z;
    int L  = slen[b];
    int start = sp * CHUNK;
    if (start >= L) return;
    int end = min(start + CHUNK, L);
    int n   = end - start;

    int tid  = threadIdx.x;
    int w    = tid >> 5;
    int lane = tid & 31;
    int myloc = loc[b];
    int rbase = rpi[b] * SS;

    __shared__ __align__(16) float qs[GG][DD];   // 2 KB
    __shared__ float sc[GG][CHUNK];              // 4 KB (scores -> probs)
    __shared__ float buf[2][GG][DD];             // 4 KB (PV parity reduce)
    __shared__ int   tok_s[CHUNK];               // 1 KB
    __shared__ float red[8];

    for (int i = tid; i < GG * DD; i += 256)
        qs[i >> 7][i & 127] = g_qbuf[(b * HQ + kv * GG + (i >> 7)) * DD + (i & 127)];
    for (int t = tid; t < n; t += 256)
        tok_s[t] = r2t[rbase + start + t];
    __syncthreads();

    // Phase 1: scores (q pre-scaled). One warp per token; coalesced 512B K-row.
    const float* knewp = g_knew + (b * HKV + kv) * DD;
    for (int t0 = w; t0 < n; t0 += 8) {
        int tk = tok_s[t0];
        const float* kp = (tk == myloc) ? knewp
                                        : (kc + ((size_t)tk * HKV + kv) * DD);
        float4 k4 = *((const float4*)kp + lane);
        float4 q0 = *((const float4*)&qs[0][0] + lane);
        float4 q1 = *((const float4*)&qs[1][0] + lane);
        float4 q2 = *((const float4*)&qs[2][0] + lane);
        float4 q3 = *((const float4*)&qs[3][0] + lane);
        float s0 = k4.x * q0.x + k4.y * q0.y + k4.z * q0.z + k4.w * q0.w;
        float s1 = k4.x * q1.x + k4.y * q1.y + k4.z * q1.z + k4.w * q1.w;
        float s2 = k4.x * q2.x + k4.y * q2.y + k4.z * q2.z + k4.w * q2.w;
        float s3 = k4.x * q3.x + k4.y * q3.y + k4.z * q3.z + k4.w * q3.w;
#pragma unroll
        for (int o = 16; o > 0; o >>= 1) {
            s0 += __shfl_xor_sync(0xffffffffu, s0, o);
            s1 += __shfl_xor_sync(0xffffffffu, s1, o);
            s2 += __shfl_xor_sync(0xffffffffu, s2, o);
            s3 += __shfl_xor_sync(0xffffffffu, s3, o);
        }
        if (lane == 0) {
            sc[0][t0] = s0; sc[1][t0] = s1; sc[2][t0] = s2; sc[3][t0] = s3;
        }
    }
    __syncthreads();

    // Phase 2: per-g chunk max, exp, sum; store (m, l).
    int mlbase = ((b * HKV + kv) * NSPLIT + sp) * GG;
#pragma unroll
    for (int g = 0; g < GG; g++) {
        float v  = (tid < n) ? sc[g][tid] : -FLT_MAX;
        float mv = v;
#pragma unroll
        for (int o = 16; o > 0; o >>= 1)
            mv = fmaxf(mv, __shfl_xor_sync(0xffffffffu, mv, o));
        if (lane == 0) red[w] = mv;
        __syncthreads();
        float mg = red[0];
#pragma unroll
        for (int i = 1; i < 8; i++) mg = fmaxf(mg, red[i]);
        float e = (tid < n) ? __expf(v - mg) : 0.f;
        if (tid < n) sc[g][tid] = e;
        float sv = e;
#pragma unroll
        for (int o = 16; o > 0; o >>= 1)
            sv += __shfl_xor_sync(0xffffffffu, sv, o);
        __syncthreads();                 // all mg reads done before overwrite
        if (lane == 0) red[w] = sv;
        __syncthreads();
        if (tid == 0) {
            float lg = 0.f;
#pragma unroll
            for (int i = 0; i < 8; i++) lg += red[i];
            g_pm[mlbase + g] = mg;
            g_pl[mlbase + g] = lg;
        }
        __syncthreads();                 // protect red for next g
    }

    // Phase 3: PV. 2 tokens in flight (parity) x 128 d-threads; each thread
    // accumulates ALL 4 head-groups -> V row loaded once per token.
    int tp = tid >> 7;       // token parity
    int d  = tid & 127;
    float a0 = 0.f, a1 = 0.f, a2 = 0.f, a3 = 0.f;
    const float* vnewp = g_vnew + (b * HKV + kv) * DD;
#pragma unroll 4
    for (int t = tp; t < n; t += 2) {
        int tk = tok_s[t];
        const float* vp = (tk == myloc) ? vnewp
                                        : (vc + ((size_t)tk * HKV + kv) * DD);
        float vv = vp[d];
        a0 = fmaf(sc[0][t], vv, a0);
        a1 = fmaf(sc[1][t], vv, a1);
        a2 = fmaf(sc[2][t], vv, a2);
        a3 = fmaf(sc[3][t], vv, a3);
    }
    buf[tp][0][d] = a0; buf[tp][1][d] = a1;
    buf[tp][2][d] = a2; buf[tp][3][d] = a3;
    __syncthreads();

    if (tid < DD) {
        int ob = ((b * HKV + kv) * NSPLIT + sp) * GG * DD;
#pragma unroll
        for (int g = 0; g < GG; g++)
            g_po[ob + g * DD + tid] = buf[0][g][tid] + buf[1][g][tid];
    }
}

// ---------------- combine splits (logsumexp) --------------------------------
__global__ void __launch_bounds__(128)
combine_kernel(const int* __restrict__ slen)
{
    int b = blockIdx.x;
    int h = blockIdx.y;            // 0..15 global q head
    int kv = h >> 2, g = h & 3;
    int d  = threadIdx.x;
    int L  = slen[b];
    int ns = (L + CHUNK - 1) / CHUNK;

    int mlbase = ((b * HKV + kv) * NSPLIT) * GG + g;
    float M = -FLT_MAX;
    for (int i = 0; i < ns; i++) M = fmaxf(M, g_pm[mlbase + i * GG]);

    float denom = 0.f, acc = 0.f;
    int obase = ((b * HKV + kv) * NSPLIT) * GG * DD + g * DD + d;
    for (int i = 0; i < ns; i++) {
        float wgt = __expf(g_pm[mlbase + i * GG] - M);
        denom += wgt * g_pl[mlbase + i * GG];
        acc   += wgt * g_po[obase + i * GG * DD];
    }
    g_attn[(b * HQ + h) * DD + d] = acc / denom;
}

// ---------------- Wo split-K reduce -> final output -------------------------
__global__ void __launch_bounds__(256)
wo_reduce(float* __restrict__ out)
{
    int i = blockIdx.x * 256 + threadIdx.x;   // 0..131071
    float s = 0.f;
#pragma unroll
    for (int k = 0; k < SKN; k++)
        s += g_wo_part[(size_t)k * BB * HH + i];
    out[i] = s;
}

// ---------------- launch -----------------------------------------------------
extern "C" void kernel_launch(void* const* d_in, const int* in_sizes, int n_in,
                              void* d_out, int out_size)
{
    const float* hid  = (const float*)d_in[0];
    const float* Wq   = (const float*)d_in[1];
    const float* Wk   = (const float*)d_in[2];
    const float* Wv   = (const float*)d_in[3];
    const float* qw   = (const float*)d_in[4];
    const float* kw   = (const float*)d_in[5];
    const float* Wo   = (const float*)d_in[6];
    const float* kc   = (const float*)d_in[7];
    const float* vc   = (const float*)d_in[8];
    const float* cosp = (const float*)d_in[9];
    const float* sinp = (const float*)d_in[10];
    const int*   r2t  = (const int*)d_in[11];
    const int*   rpi  = (const int*)d_in[12];
    const int*   slen = (const int*)d_in[13];
    const int*   loc  = (const int*)d_in[14];
    float* out = (float*)d_out;

    sgemm_part<0><<<dim3(CQKV / 128, SKN), 256>>>(hid, Wq, Wk, Wv, HH, HH + HKV * DD, CQKV);
    rms_rope_kernel<<<dim3(BB, HQ + 2 * HKV), 128>>>(qw, kw, cosp, sinp);
    attn_partial<<<dim3(BB, HKV, NSPLIT), 256>>>(kc, vc, r2t, rpi, slen, loc);
    combine_kernel<<<dim3(BB, HQ), 128>>>(slen);
    sgemm_part<1><<<dim3(HH / 128, SKN), 256>>>(nullptr, Wo, Wo, Wo, 2 * HH, 2 * HH, HH);
    wo_reduce<<<BB * HH / 256, 256>>>(out);
}